// round 9
// baseline (speedup 1.0000x reference)
#include <cuda_runtime.h>
#include <cuda_bf16.h>

#define NB 32
#define WPB 8
#define THREADS (WPB * 32)
#define STRIDE 36   // padded row; floats [32..35] of row j hold h[j] (overlay)

__device__ __forceinline__ float clamp01(float x) {
    return fminf(fmaxf(x, 0.0f), 1.0f);
}

__device__ __forceinline__ void cp_async16(float* smem_dst, const float* gmem_src) {
    unsigned sa = (unsigned)__cvta_generic_to_shared(smem_dst);
    asm volatile("cp.async.cg.shared.global [%0], [%1], 16;\n"
                 :: "r"(sa), "l"(gmem_src) : "memory");
}

__global__ __launch_bounds__(THREADS, 6)
void BioTokenMucusSim_kernel(const float* __restrict__ h,
                             const float* __restrict__ W,
                             const float* __restrict__ stim,
                             float* __restrict__ h_out,
                             float* __restrict__ W_out,
                             int n_pairs)
{
    // 8 warps x 32 rows x 36 floats = 36864 B/block -> 6 blocks/SM, 48 warps
    __shared__ float wsh[WPB][NB * STRIDE];

    const int warp = threadIdx.x >> 5;
    const int lane = threadIdx.x & 31;
    const int qr = lane >> 3;        // row-in-group
    const int qc = (lane & 7) * 4;   // float4 col offset
    float* ws = wsh[warp];

    const int total_warps = gridDim.x * WPB;      // 7104: persistent, one wave
    int pair = blockIdx.x * WPB + warp;
    if (pair >= n_pairs) return;

    // ---- prologue: load first tile + h + stim ----
    {
        const float* Wp = W + (size_t)pair * (NB * NB);
        #pragma unroll
        for (int t = 0; t < 8; ++t) {
            const int r = t * 4 + qr;
            cp_async16(ws + r * STRIDE + qc, Wp + r * NB + qc);
        }
        cp_async16(ws + lane * STRIDE + 32, h + (size_t)pair * NB * 4 + lane * 4);
        asm volatile("cp.async.commit_group;\n" ::: "memory");
    }
    float s_cur = stim[(size_t)pair * NB + lane];

    for (; pair < n_pairs; pair += total_warps) {
        const int  npair    = pair + total_warps;
        const bool has_next = (npair < n_pairs);

        // ---- current tile ready? ----
        asm volatile("cp.async.wait_group 0;\n" ::: "memory");
        __syncwarp();

        // diag := 0 (update pass forces it 0 anyway); read own h back
        ws[lane * STRIDE + lane] = 0.0f;
        const float4 hv = *(const float4*)(ws + lane * STRIDE + 32);
        __syncwarp();

        // ---- masked matvec: row from shared, h via 1-wf broadcasts ----
        float ifx = 0.f, ify = 0.f, ifz = 0.f, ifw = 0.f, wsum = 0.f;
        #pragma unroll
        for (int t = 0; t < 8; ++t) {
            const float4 w4 = *(const float4*)(ws + lane * STRIDE + t * 4);
            const float wq[4] = {w4.x, w4.y, w4.z, w4.w};
            #pragma unroll
            for (int e = 0; e < 4; ++e) {
                const int j = t * 4 + e;
                const float4 hj = *(const float4*)(ws + j * STRIDE + 32);
                ifx  += wq[e] * hj.x;
                ify  += wq[e] * hj.y;
                ifz  += wq[e] * hj.z;
                ifw  += wq[e] * hj.w;
                wsum += wq[e];
            }
        }
        const float inv = 1.0f / (wsum + 1e-8f);
        const float En = ifx * inv, Pn = ify * inv, Gn = ifz * inv, Ln = ifw * inv;

        // ---- channel update ----
        const float E = hv.x, P = hv.y, G = hv.z, L = hv.w;
        const float E_new = clamp01(E + 0.3f * s_cur - 0.4f * P - 0.2f * G);
        const float P_new = clamp01(P + 0.5f * s_cur + 0.3f * (Pn - P) - 0.2f * E);
        const float G_new = clamp01(G + 0.4f * E * (1.0f - P) + 0.2f * (Gn - G) - 0.3f * P);
        const float good  = 0.5f * En + 0.5f * Gn;
        const float L_new = clamp01(L + 0.4f * good + 0.3f * (Ln - L) - 0.3f * P);

        const float4 hn = make_float4(E_new, P_new, G_new, L_new);
        ((float4*)(h_out + (size_t)pair * NB * 4))[lane] = hn;

        __syncwarp();                                  // matvec h reads done
        *(float4*)(ws + lane * STRIDE + 32) = hn;      // publish h_new
        __syncwarp();

        // ---- prefetch next stim early (register, scoreboard-covered) ----
        float s_next = 0.0f;
        if (has_next) s_next = stim[(size_t)npair * NB + lane];

        // ---- fused W-update + store, with IN-PLACE prefetch of next tile:
        //      row-group t of W is dead after its read -> cp.async next W there
        float4 hj4[4];
        #pragma unroll
        for (int e = 0; e < 4; ++e)
            hj4[e] = *(const float4*)(ws + (qc + e) * STRIDE + 32);

        float* Wo = W_out + (size_t)pair * (NB * NB);
        const float* Wn = W + (size_t)npair * (NB * NB);
        #pragma unroll
        for (int t = 0; t < 8; ++t) {
            const int r = t * 4 + qr;
            const float4 w  = *(const float4*)(ws + r * STRIDE + qc);
            const float4 hr = *(const float4*)(ws + r * STRIDE + 32);
            const float wq[4] = {w.x, w.y, w.z, w.w};
            float out[4];
            #pragma unroll
            for (int e = 0; e < 4; ++e) {
                const float dx = hr.x - hj4[e].x, dy = hr.y - hj4[e].y;
                const float dz = hr.z - hj4[e].z, dw = hr.w - hj4[e].w;
                const float sq = dx * dx + dy * dy + dz * dz + dw * dw;
                const float dist = (sq > 0.0f) ? sq * rsqrtf(sq) : 0.0f;
                float wn = fmaf(0.05f * (hr.w + hj4[e].w), dist, 0.95f * wq[e]);
                wn = clamp01(wn);
                if (r == qc + e) wn = 0.0f;            // diagonal
                out[e] = wn;
            }
            *(float4*)(Wo + r * NB + qc) = make_float4(out[0], out[1], out[2], out[3]);

            // own W cell consumed above -> safe to start next pair's fetch here
            if (has_next)
                cp_async16(ws + r * STRIDE + qc, Wn + r * NB + qc);
        }

        // pads (h overlay) read complete across the warp before overwriting
        __syncwarp();
        if (has_next)
            cp_async16(ws + lane * STRIDE + 32, h + (size_t)npair * NB * 4 + lane * 4);
        asm volatile("cp.async.commit_group;\n" ::: "memory");

        s_cur = s_next;
    }
}

extern "C" void kernel_launch(void* const* d_in, const int* in_sizes, int n_in,
                              void* d_out, int out_size) {
    const float* h    = (const float*)d_in[0];  // [B,S,32,4]
    const float* W    = (const float*)d_in[1];  // [B,S,32,32]
    const float* stim = (const float*)d_in[2];  // [B,S,32]

    const int n_pairs = in_sizes[2] / NB;       // B*S = 16384

    float* h_out = (float*)d_out;                       // h_new first
    float* W_out = (float*)d_out + (size_t)in_sizes[0]; // then W_new

    // persistent: 6 blocks/SM x 148 SMs = 888 blocks, one wave, warp-stride
    const int blocks = 888;
    BioTokenMucusSim_kernel<<<blocks, THREADS>>>(h, W, stim, h_out, W_out, n_pairs);
}